// round 15
// baseline (speedup 1.0000x reference)
#include <cuda_runtime.h>
#include <cstdint>

#define BATCH   16384
#define NCONDS  50
#define EMB_DIM 64
#define IN_ROW  (1 + NCONDS)             // 51 int32 per batch row
#define OUT_ROW ((1 + NCONDS) * EMB_DIM) // 3264 floats per batch row
#define PF      4                        // software-pipeline depth
#define NSTAGE  (NCONDS / 2)             // 25 stages, 2 conds per stage

// Write-through 128-bit store: bypasses L2 write-allocate so the 214 MB
// output stream doesn't occupy LTS/L2 alongside the gather reads.
__device__ __forceinline__ void stwt128(float* p, float4 v) {
    asm volatile("st.global.wt.v4.f32 [%0], {%1, %2, %3, %4};"
                 :: "l"(p), "f"(v.x), "f"(v.y), "f"(v.z), "f"(v.w)
                 : "memory");
}
__device__ __forceinline__ void stwt64(float* p, float2 v) {
    asm volatile("st.global.wt.v2.f32 [%0], {%1, %2};"
                 :: "l"(p), "f"(v.x), "f"(v.y) : "memory");
}

// Single-pass, one warp per batch row; each half-warp (16 lanes x float4)
// owns one condition per stage. PF-deep register prefetch ring; fused
// 5-shfl dual reduction; write-through output stores.
__global__ void __launch_bounds__(256, 8)
cond_filter_kernel(const int* __restrict__ inp,
                   const float* __restrict__ table,
                   float* __restrict__ out)
{
    const int warp = (blockIdx.x * blockDim.x + threadIdx.x) >> 5;
    const int lane = threadIdx.x & 31;
    if (warp >= BATCH) return;

    const int hl   = lane & 15;          // lane within half-warp
    const int half = lane >> 4;          // which half-warp (0/1)
    const bool hi8 = (lane & 8) != 0;    // high 8-lane subgroup of the half

    const int* __restrict__ row  = inp + (size_t)warp * IN_ROW;
    float* __restrict__     orow = out + (size_t)warp * OUT_ROW;

    // ---- Prologue: start PF condition gathers immediately ----
    float4 ring[PF];
    #pragma unroll
    for (int p = 0; p < PF; p++) {
        const int cidx = __ldg(row + 1 + 2 * p + half);
        ring[p] = *reinterpret_cast<const float4*>(
            table + (size_t)cidx * EMB_DIM + hl * 4);
    }

    // ---- Event: raw copy out (all 32 lanes, float2 each) + normalize ----
    const int eidx = __ldg(row);
    const float4 ev = *reinterpret_cast<const float4*>(
        table + (size_t)eidx * EMB_DIM + hl * 4);
    // Lane l writes dims [2l, 2l+2): uniform, unpredicated, coalesced 256 B.
    {
        const float2 evh = hi8 || half
            ? make_float2(0.f, 0.f) : make_float2(0.f, 0.f); // placeholder opt-out
        (void)evh;
    }
    // Simpler: each lane re-derives its float2 from the table row directly.
    {
        const float2 e2 = *reinterpret_cast<const float2*>(
            table + (size_t)eidx * EMB_DIM + lane * 2);
        stwt64(orow + lane * 2, e2);
    }

    float ss = ev.x * ev.x + ev.y * ev.y + ev.z * ev.z + ev.w * ev.w;
    #pragma unroll
    for (int o = 8; o; o >>= 1)
        ss += __shfl_xor_sync(0xffffffffu, ss, o);   // within half-warp
    const float einv = rsqrtf(ss);
    const float4 en = make_float4(ev.x * einv, ev.y * einv,
                                  ev.z * einv, ev.w * einv);

    // ---- Stages: consume s, prefetch s+PF ----
    float* __restrict__ crow = orow + EMB_DIM;
    #pragma unroll
    for (int s = 0; s < NSTAGE; s++) {
        const float4 cv = ring[s % PF];
        if (s + PF < NSTAGE) {
            const int cidx = __ldg(row + 1 + 2 * (s + PF) + half);
            ring[s % PF] = *reinterpret_cast<const float4*>(
                table + (size_t)cidx * EMB_DIM + hl * 4);
        }

        float s2 = cv.x * cv.x + cv.y * cv.y + cv.z * cv.z + cv.w * cv.w;
        float dt = cv.x * en.x + cv.y * en.y + cv.z * en.z + cv.w * en.w;

        // Fused dual reduction over the 16-lane half-warp (5 SHFLs)
        const float mine  = hi8 ? s2 : dt;
        const float other = hi8 ? dt : s2;
        float z = mine + __shfl_xor_sync(0xffffffffu, other, 8);
        #pragma unroll
        for (int o = 4; o; o >>= 1)
            z += __shfl_xor_sync(0xffffffffu, z, o);
        const float zb = __shfl_xor_sync(0xffffffffu, z, 8);
        const float dts = hi8 ? zb : z;
        const float s2s = hi8 ? z  : zb;

        const float cinv  = rsqrtf(s2s);
        const float scale = dts * cinv * cinv;   // cond_nrm * score folded

        stwt128(crow + (size_t)(2 * s + half) * EMB_DIM + hl * 4,
                make_float4(cv.x * scale, cv.y * scale,
                            cv.z * scale, cv.w * scale));
    }
}

extern "C" void kernel_launch(void* const* d_in, const int* in_sizes, int n_in,
                              void* d_out, int out_size)
{
    const int*   inp   = (const int*)d_in[0];     // (16384, 51) int32
    const float* table = (const float*)d_in[1];   // (100002, 64) float32
    float*       out   = (float*)d_out;           // (16384, 3264) float32

    const int threads = 256;                 // 8 warps/block
    const int total_threads = BATCH * 32;    // one warp per row
    const int blocks = (total_threads + threads - 1) / threads;
    cond_filter_kernel<<<blocks, threads>>>(inp, table, out);
}